// round 15
// baseline (speedup 1.0000x reference)
#include <cuda_runtime.h>

#define B_ 64
#define K_ 32
#define T_ 1280
#define C_ 16
#define E_ 64
#define CONV_CH_ 32
#define POOL_ 10
#define SEG_ 128                 // T_ / POOL_
#define FEAT_ 320                // CONV_CH_ * POOL_
#define WSEG_ 256                // warp_kernel t-tile

// scratch (no allocation allowed)
__device__ float g_warp[B_ * K_];
__device__ float g_off[B_ * K_];
__device__ float g_pool[B_ * FEAT_];

// ---------------------------------------------------------------------------
// Stage 1: conv1d(pad=2)+bias+relu+avgpool(128). Block per (pp, b).
// 8 warps: wg = w&1 -> channel half [wg*16, wg*16+16), tw = w>>1 -> t range
// [tw*32, tw*32+32). Lane: og = lane>>1 -> channel o = wg*16+og,
// q2 = lane&1 -> C-half (quads 2*q2, 2*q2+1).
// Per t: 10 broadcast LDS.128 (row warp-uniform, 2 unique addrs), 40 FFMA,
// ONE shfl to merge C-halves (was 8 shfl per 2t -> now 2 per 2t), relu, acc.
// ---------------------------------------------------------------------------
__global__ __launch_bounds__(256, 3) void conv_pool_kernel(
    const float* __restrict__ x,       // [B, T, C]
    const float* __restrict__ conv_w,  // [32, 16, 5]
    const float* __restrict__ conv_b)  // [32]
{
    __shared__ float4 sx4[(SEG_ + 4) * 4];     // 132 rows x 4 quads
    __shared__ float  sw[CONV_CH_ * 5 * C_];   // [o][kk][i]
    __shared__ float  sacc[4][CONV_CH_];       // per-tw pooled partials

    const int pp  = blockIdx.x;
    const int b   = blockIdx.y;
    const int tid = threadIdx.x;

    // stage conv weights rearranged: [o][i][kk] -> [o][kk][i]
    for (int idx = tid; idx < CONV_CH_ * C_ * 5; idx += 256) {
        int o   = idx / 80;
        int rem = idx - o * 80;
        int kk  = rem >> 4;
        int i   = rem & 15;
        sw[(o * 5 + kk) * C_ + i] = conv_w[o * 80 + i * 5 + kk];
    }

    // stage x tile: global rows pp*128-2 .. pp*128+129, zero outside [0,T)
    {
        const float4* x4 = (const float4*)(x + (size_t)b * T_ * C_);
        for (int idx = tid; idx < (SEG_ + 4) * 4; idx += 256) {
            int r = idx >> 2;
            int q = idx & 3;
            int g = pp * SEG_ - 2 + r;
            float4 v = make_float4(0.f, 0.f, 0.f, 0.f);
            if (g >= 0 && g < T_) v = x4[g * 4 + q];
            sx4[r * 4 + q] = v;
        }
    }
    __syncthreads();

    const int w    = tid >> 5;
    const int wg   = w & 1;             // channel half
    const int tw   = w >> 1;            // t range (32 t's)
    const int lane = tid & 31;
    const int og   = lane >> 1;         // channel within half
    const int q2   = lane & 1;          // C-half
    const int o    = wg * 16 + og;

    // weights: channel o, 5 taps, quads 2*q2 and 2*q2+1 -> 10 float4 (40 regs)
    float4 wreg[5][2];
    {
        const float4* sw4 = (const float4*)sw;
        #pragma unroll
        for (int kk = 0; kk < 5; ++kk)
            #pragma unroll
            for (int j = 0; j < 2; ++j)
                wreg[kk][j] = sw4[(o * 5 + kk) * 4 + q2 * 2 + j];
    }
    const float bias = conv_b[o];

    float acc = 0.f;
    const int tbase = tw * 32;
    #pragma unroll 2
    for (int tt = 0; tt < 16; ++tt) {
        const int ra = tbase + tt;      // tile row of tap kk=0 (t pair A)
        const int rb = ra + 16;         // t pair B
        float va = 0.f, vb = 0.f;
        #pragma unroll
        for (int kk = 0; kk < 5; ++kk) {
            float4 xa0 = sx4[(ra + kk) * 4 + q2 * 2 + 0];
            float4 xa1 = sx4[(ra + kk) * 4 + q2 * 2 + 1];
            float4 xb0 = sx4[(rb + kk) * 4 + q2 * 2 + 0];
            float4 xb1 = sx4[(rb + kk) * 4 + q2 * 2 + 1];
            va = fmaf(xa0.x, wreg[kk][0].x, va); va = fmaf(xa0.y, wreg[kk][0].y, va);
            va = fmaf(xa0.z, wreg[kk][0].z, va); va = fmaf(xa0.w, wreg[kk][0].w, va);
            va = fmaf(xa1.x, wreg[kk][1].x, va); va = fmaf(xa1.y, wreg[kk][1].y, va);
            va = fmaf(xa1.z, wreg[kk][1].z, va); va = fmaf(xa1.w, wreg[kk][1].w, va);
            vb = fmaf(xb0.x, wreg[kk][0].x, vb); vb = fmaf(xb0.y, wreg[kk][0].y, vb);
            vb = fmaf(xb0.z, wreg[kk][0].z, vb); vb = fmaf(xb0.w, wreg[kk][0].w, vb);
            vb = fmaf(xb1.x, wreg[kk][1].x, vb); vb = fmaf(xb1.y, wreg[kk][1].y, vb);
            vb = fmaf(xb1.z, wreg[kk][1].z, vb); vb = fmaf(xb1.w, wreg[kk][1].w, vb);
        }
        // merge the two C-halves (lanes q2=0/1), both lanes get the full sum
        va += __shfl_xor_sync(0xffffffffu, va, 1);
        vb += __shfl_xor_sync(0xffffffffu, vb, 1);
        acc += fmaxf(va + bias, 0.f) + fmaxf(vb + bias, 0.f);
    }

    if (q2 == 0) sacc[tw][o] = acc;
    __syncthreads();
    if (tid < CONV_CH_) {
        float s = sacc[0][tid] + sacc[1][tid] + sacc[2][tid] + sacc[3][tid];
        g_pool[b * FEAT_ + tid * POOL_ + pp] = s * (1.f / SEG_);
    }
}

// ---------------------------------------------------------------------------
// Stage 2: linear+relu -> embed, then per-class warp/off scalars. Block per b.
// ---------------------------------------------------------------------------
__global__ __launch_bounds__(64) void head_kernel(
    const float* __restrict__ lin_w,   // [64, 320]
    const float* __restrict__ lin_b,   // [64]
    const float* __restrict__ warp_W,  // [32, 64]
    const float* __restrict__ warp_b,  // [32]
    const float* __restrict__ off_W,   // [32, 64]
    const float* __restrict__ off_b,   // [32]
    float* __restrict__ out_warp,      // tail of d_out
    float* __restrict__ out_off)
{
    __shared__ float4 sp[FEAT_ / 4];
    __shared__ float semb[E_];

    const int b   = blockIdx.x;
    const int tid = threadIdx.x;

    {
        const float4* gp = (const float4*)(g_pool + b * FEAT_);
        for (int j = tid; j < FEAT_ / 4; j += 64) sp[j] = gp[j];
    }
    __syncthreads();

    {
        const float4* wr = (const float4*)(lin_w + (size_t)tid * FEAT_);
        float a0 = lin_b[tid], a1 = 0.f;
        #pragma unroll 4
        for (int j = 0; j < FEAT_ / 4; j += 2) {
            float4 w0 = wr[j],   p0 = sp[j];
            float4 w1 = wr[j+1], p1 = sp[j+1];
            a0 = fmaf(w0.x, p0.x, a0); a0 = fmaf(w0.y, p0.y, a0);
            a0 = fmaf(w0.z, p0.z, a0); a0 = fmaf(w0.w, p0.w, a0);
            a1 = fmaf(w1.x, p1.x, a1); a1 = fmaf(w1.y, p1.y, a1);
            a1 = fmaf(w1.z, p1.z, a1); a1 = fmaf(w1.w, p1.w, a1);
        }
        semb[tid] = fmaxf(a0 + a1, 0.f);
    }
    __syncthreads();

    if (tid < K_) {
        const float* wW = warp_W + tid * E_;
        const float* oW = off_W + tid * E_;
        float aw = warp_b[tid];
        float ao = off_b[tid];
        #pragma unroll
        for (int e = 0; e < E_; ++e) {
            float em = semb[e];
            aw = fmaf(wW[e], em, aw);
            ao = fmaf(oW[e], em, ao);
        }
        const int bk = b * K_ + tid;
        g_warp[bk] = aw;
        g_off[bk]  = ao;
        out_warp[bk] = aw;
        out_off[bk]  = ao;
    }
}

// ---------------------------------------------------------------------------
// Stage 3: warped output. blockIdx.y = bk, blockIdx.x = 256-t tile.
// Prototype rows for the tile are contiguous (idx monotone, block-uniform w):
// stage once in smem (halves LTS read traffic), then 4 float4/thread with all
// LDS issued before the stores (MLP), plain STG (let L2 absorb writes).
// ---------------------------------------------------------------------------
__global__ __launch_bounds__(256) void warp_kernel(
    const float* __restrict__ proto,   // [K, T, C]
    float4* __restrict__ out)          // [B, K, T, C] as float4
{
    __shared__ float4 sp[(WSEG_ + 2) * 4];     // up to 258 rows x 4 quads

    const int bk = blockIdx.y;
    const int k  = bk & (K_ - 1);
    const float w = g_warp[bk];
    const float o = g_off[bk];
    const int t0 = blockIdx.x * WSEG_;

    // contiguous row range for this tile
    const float idx_lo = fminf(fmaxf((float)t0 - w, 0.f), (float)(T_ - 1));
    const float idx_hi = fminf(fmaxf((float)(t0 + WSEG_ - 1) - w, 0.f), (float)(T_ - 1));
    const int r_lo = (int)floorf(idx_lo);
    const int r_hi = min((int)floorf(idx_hi) + 1, T_ - 1);
    const int n4   = (r_hi - r_lo + 1) * 4;    // <= 1032 float4

    const float4* pk = (const float4*)(proto + (size_t)k * T_ * C_);
    for (int i = threadIdx.x; i < n4; i += 256)
        sp[i] = pk[r_lo * 4 + i];
    __syncthreads();

    const int q  = threadIdx.x & 3;
    const int tl = threadIdx.x >> 2;           // 0..63
    float4* ob = out + ((size_t)bk * T_) * 4;

    int   i0[4], i1[4];
    float fr[4];
    #pragma unroll
    for (int h = 0; h < 4; ++h) {
        const int t = t0 + tl + h * 64;
        float idx = fminf(fmaxf((float)t - w, 0.f), (float)(T_ - 1));
        float i0f = floorf(idx);
        i0[h] = (int)i0f - r_lo;
        i1[h] = min((int)i0f + 1, T_ - 1) - r_lo;
        fr[h] = idx - i0f;
    }

    float4 a[4], c[4];
    #pragma unroll
    for (int h = 0; h < 4; ++h) {
        a[h] = sp[i0[h] * 4 + q];
        c[h] = sp[i1[h] * 4 + q];
    }

    #pragma unroll
    for (int h = 0; h < 4; ++h) {
        const int t = t0 + tl + h * 64;
        const float f = fr[h];
        float4 res;
        res.x = fmaf(f, c[h].x - a[h].x, a[h].x) + o;
        res.y = fmaf(f, c[h].y - a[h].y, a[h].y) + o;
        res.z = fmaf(f, c[h].z - a[h].z, a[h].z) + o;
        res.w = fmaf(f, c[h].w - a[h].w, a[h].w) + o;
        ob[t * 4 + q] = res;
    }
}

extern "C" void kernel_launch(void* const* d_in, const int* in_sizes, int n_in,
                              void* d_out, int out_size) {
    const float* x       = (const float*)d_in[0];
    const float* proto   = (const float*)d_in[1];
    const float* conv_w  = (const float*)d_in[2];
    const float* conv_b  = (const float*)d_in[3];
    const float* lin_w   = (const float*)d_in[4];
    const float* lin_b   = (const float*)d_in[5];
    const float* warp_W  = (const float*)d_in[6];
    const float* warp_b  = (const float*)d_in[7];
    const float* off_W   = (const float*)d_in[8];
    const float* off_b   = (const float*)d_in[9];

    float* out = (float*)d_out;
    const size_t warped_elems = (size_t)B_ * K_ * T_ * C_; // 41,943,040
    float* out_warp = out + warped_elems;
    float* out_off  = out_warp + (size_t)B_ * K_;

    dim3 g1(POOL_, B_);
    conv_pool_kernel<<<g1, 256>>>(x, conv_w, conv_b);

    head_kernel<<<B_, 64>>>(lin_w, lin_b, warp_W, warp_b, off_W, off_b,
                            out_warp, out_off);

    dim3 g3(T_ / WSEG_, B_ * K_);
    warp_kernel<<<g3, 256>>>(proto, (float4*)out);
}

// round 16
// speedup vs baseline: 1.0367x; 1.0367x over previous
#include <cuda_runtime.h>

#define B_ 64
#define K_ 32
#define T_ 1280
#define C_ 16
#define E_ 64
#define CONV_CH_ 32
#define POOL_ 10
#define SEG_ 128                 // T_ / POOL_
#define FEAT_ 320                // CONV_CH_ * POOL_
#define WT_ 64                   // warp_kernel t-tile

// scratch (no allocation allowed)
__device__ float g_warp[B_ * K_];
__device__ float g_off[B_ * K_];
__device__ float g_pool[B_ * FEAT_];

// ---------------------------------------------------------------------------
// Stage 1 (R13 version, best measured): conv1d(pad=2)+bias+relu+avgpool(128).
// Block per (pp, b). 8 warps: wg = w&1 channel half, tw = w>>1 t-range of 32.
// Lane: og=lane>>2, q=lane&3; thread owns channels o0,o0+1, quad q.
// t-pairs (tt, tt+16): 4 independent FMA chains + batched shfl reductions.
// ---------------------------------------------------------------------------
__global__ __launch_bounds__(256, 3) void conv_pool_kernel(
    const float* __restrict__ x,       // [B, T, C]
    const float* __restrict__ conv_w,  // [32, 16, 5]
    const float* __restrict__ conv_b)  // [32]
{
    __shared__ float4 sx4[(SEG_ + 4) * 4];     // 132 rows x 4 quads
    __shared__ float  sw[CONV_CH_ * 5 * C_];   // [o][kk][i]
    __shared__ float  sacc[4][CONV_CH_];       // per-tw pooled partials

    const int pp  = blockIdx.x;
    const int b   = blockIdx.y;
    const int tid = threadIdx.x;

    // stage conv weights rearranged: [o][i][kk] -> [o][kk][i]
    for (int idx = tid; idx < CONV_CH_ * C_ * 5; idx += 256) {
        int o   = idx / 80;
        int rem = idx - o * 80;
        int kk  = rem >> 4;
        int i   = rem & 15;
        sw[(o * 5 + kk) * C_ + i] = conv_w[o * 80 + i * 5 + kk];
    }

    // stage x tile: global rows pp*128-2 .. pp*128+129, zero outside [0,T)
    {
        const float4* x4 = (const float4*)(x + (size_t)b * T_ * C_);
        for (int idx = tid; idx < (SEG_ + 4) * 4; idx += 256) {
            int r = idx >> 2;
            int q = idx & 3;
            int g = pp * SEG_ - 2 + r;
            float4 v = make_float4(0.f, 0.f, 0.f, 0.f);
            if (g >= 0 && g < T_) v = x4[g * 4 + q];
            sx4[r * 4 + q] = v;
        }
    }
    __syncthreads();

    const int w    = tid >> 5;
    const int wg   = w & 1;             // channel half
    const int tw   = w >> 1;            // t range (32 t's)
    const int lane = tid & 31;
    const int og   = lane >> 2;
    const int q    = lane & 3;
    const int o0   = wg * 16 + og * 2;

    // weights: 2 channels x 5 taps, quad q -> 10 float4 (40 regs)
    float4 wreg[2][5];
    {
        const float4* sw4 = (const float4*)sw;
        #pragma unroll
        for (int j = 0; j < 2; ++j)
            #pragma unroll
            for (int kk = 0; kk < 5; ++kk)
                wreg[j][kk] = sw4[((o0 + j) * 5 + kk) * 4 + q];
    }
    const float bias0 = conv_b[o0];
    const float bias1 = conv_b[o0 + 1];

    float acc0 = 0.f, acc1 = 0.f;
    const int tbase = tw * 32;
    #pragma unroll 2
    for (int tt = 0; tt < 16; ++tt) {
        const int ra = tbase + tt;
        const int rb = ra + 16;
        float va0 = 0.f, va1 = 0.f, vb0 = 0.f, vb1 = 0.f;
        #pragma unroll
        for (int kk = 0; kk < 5; ++kk) {
            float4 xa = sx4[(ra + kk) * 4 + q];   // broadcast across og
            float4 xb = sx4[(rb + kk) * 4 + q];
            va0 = fmaf(xa.x, wreg[0][kk].x, va0); va0 = fmaf(xa.y, wreg[0][kk].y, va0);
            va0 = fmaf(xa.z, wreg[0][kk].z, va0); va0 = fmaf(xa.w, wreg[0][kk].w, va0);
            va1 = fmaf(xa.x, wreg[1][kk].x, va1); va1 = fmaf(xa.y, wreg[1][kk].y, va1);
            va1 = fmaf(xa.z, wreg[1][kk].z, va1); va1 = fmaf(xa.w, wreg[1][kk].w, va1);
            vb0 = fmaf(xb.x, wreg[0][kk].x, vb0); vb0 = fmaf(xb.y, wreg[0][kk].y, vb0);
            vb0 = fmaf(xb.z, wreg[0][kk].z, vb0); vb0 = fmaf(xb.w, wreg[0][kk].w, vb0);
            vb1 = fmaf(xb.x, wreg[1][kk].x, vb1); vb1 = fmaf(xb.y, wreg[1][kk].y, vb1);
            vb1 = fmaf(xb.z, wreg[1][kk].z, vb1); vb1 = fmaf(xb.w, wreg[1][kk].w, vb1);
        }
        va0 += __shfl_xor_sync(0xffffffffu, va0, 1);
        va1 += __shfl_xor_sync(0xffffffffu, va1, 1);
        vb0 += __shfl_xor_sync(0xffffffffu, vb0, 1);
        vb1 += __shfl_xor_sync(0xffffffffu, vb1, 1);
        va0 += __shfl_xor_sync(0xffffffffu, va0, 2);
        va1 += __shfl_xor_sync(0xffffffffu, va1, 2);
        vb0 += __shfl_xor_sync(0xffffffffu, vb0, 2);
        vb1 += __shfl_xor_sync(0xffffffffu, vb1, 2);
        acc0 += fmaxf(va0 + bias0, 0.f) + fmaxf(vb0 + bias0, 0.f);
        acc1 += fmaxf(va1 + bias1, 0.f) + fmaxf(vb1 + bias1, 0.f);
    }

    if (q == 0) {
        sacc[tw][o0]     = acc0;
        sacc[tw][o0 + 1] = acc1;
    }
    __syncthreads();
    if (tid < CONV_CH_) {
        float s = sacc[0][tid] + sacc[1][tid] + sacc[2][tid] + sacc[3][tid];
        g_pool[b * FEAT_ + tid * POOL_ + pp] = s * (1.f / SEG_);
    }
}

// ---------------------------------------------------------------------------
// Stage 2: linear+relu -> embed, then per-class warp/off scalars. Block per b.
// ---------------------------------------------------------------------------
__global__ __launch_bounds__(64) void head_kernel(
    const float* __restrict__ lin_w,   // [64, 320]
    const float* __restrict__ lin_b,   // [64]
    const float* __restrict__ warp_W,  // [32, 64]
    const float* __restrict__ warp_b,  // [32]
    const float* __restrict__ off_W,   // [32, 64]
    const float* __restrict__ off_b,   // [32]
    float* __restrict__ out_warp,      // tail of d_out
    float* __restrict__ out_off)
{
    __shared__ float4 sp[FEAT_ / 4];
    __shared__ float semb[E_];

    const int b   = blockIdx.x;
    const int tid = threadIdx.x;

    {
        const float4* gp = (const float4*)(g_pool + b * FEAT_);
        for (int j = tid; j < FEAT_ / 4; j += 64) sp[j] = gp[j];
    }
    __syncthreads();

    {
        const float4* wr = (const float4*)(lin_w + (size_t)tid * FEAT_);
        float a0 = lin_b[tid], a1 = 0.f;
        #pragma unroll 4
        for (int j = 0; j < FEAT_ / 4; j += 2) {
            float4 w0 = wr[j],   p0 = sp[j];
            float4 w1 = wr[j+1], p1 = sp[j+1];
            a0 = fmaf(w0.x, p0.x, a0); a0 = fmaf(w0.y, p0.y, a0);
            a0 = fmaf(w0.z, p0.z, a0); a0 = fmaf(w0.w, p0.w, a0);
            a1 = fmaf(w1.x, p1.x, a1); a1 = fmaf(w1.y, p1.y, a1);
            a1 = fmaf(w1.z, p1.z, a1); a1 = fmaf(w1.w, p1.w, a1);
        }
        semb[tid] = fmaxf(a0 + a1, 0.f);
    }
    __syncthreads();

    if (tid < K_) {
        const float* wW = warp_W + tid * E_;
        const float* oW = off_W + tid * E_;
        float aw = warp_b[tid];
        float ao = off_b[tid];
        #pragma unroll
        for (int e = 0; e < E_; ++e) {
            float em = semb[e];
            aw = fmaf(wW[e], em, aw);
            ao = fmaf(oW[e], em, ao);
        }
        const int bk = b * K_ + tid;
        g_warp[bk] = aw;
        g_off[bk]  = ao;
        out_warp[bk] = aw;
        out_off[bk]  = ao;
    }
}

// ---------------------------------------------------------------------------
// Stage 3: warped output, k-major. Block = (t-tile of 64, k). The ENTIRE
// prototype k (80KB) is staged once in dynamic smem; all 64 (w,off) scalars
// preloaded; then loop over b: 1 idx + 2 conflict-free LDS + 1 coalesced
// STG.128 per thread per b (b unrolled x2 for store MLP). Proto LTS reads
// collapse 135MB -> 25MB; stores become the only wall.
// ---------------------------------------------------------------------------
__global__ __launch_bounds__(256, 2) void warp_kernel(
    const float* __restrict__ proto,   // [K, T, C]
    float4* __restrict__ out)          // [B, K, T, C] as float4
{
    extern __shared__ float4 sp[];     // T_ * 4 float4 = 80KB
    __shared__ float swv[B_], sov[B_];

    const int k  = blockIdx.y;
    const int t0 = blockIdx.x * WT_;
    const int tid = threadIdx.x;

    // stage entire prototype k
    {
        const float4* pk = (const float4*)(proto + (size_t)k * T_ * C_);
        #pragma unroll 4
        for (int i = tid; i < T_ * 4; i += 256)
            sp[i] = pk[i];
    }
    // stage per-b scalars
    if (tid < B_)            swv[tid]      = g_warp[tid * K_ + k];
    else if (tid < 2 * B_)   sov[tid - B_] = g_off[(tid - B_) * K_ + k];
    __syncthreads();

    const int q  = tid & 3;
    const int tl = tid >> 2;                   // 0..63
    const int t  = t0 + tl;
    const float tf = (float)t;

    #pragma unroll 2
    for (int b = 0; b < B_; b += 2) {
        #pragma unroll
        for (int bb = 0; bb < 2; ++bb) {
            const int bi = b + bb;
            const float w = swv[bi];
            const float o = sov[bi];
            float idx = fminf(fmaxf(tf - w, 0.f), (float)(T_ - 1));
            float i0f = floorf(idx);
            int   i0  = (int)i0f;
            int   i1  = min(i0 + 1, T_ - 1);
            float f   = idx - i0f;

            float4 a = sp[i0 * 4 + q];
            float4 c = sp[i1 * 4 + q];
            float4 res;
            res.x = fmaf(f, c.x - a.x, a.x) + o;
            res.y = fmaf(f, c.y - a.y, a.y) + o;
            res.z = fmaf(f, c.z - a.z, a.z) + o;
            res.w = fmaf(f, c.w - a.w, a.w) + o;
            out[((size_t)(bi * K_ + k) * T_ + t) * 4 + q] = res;
        }
    }
}

extern "C" void kernel_launch(void* const* d_in, const int* in_sizes, int n_in,
                              void* d_out, int out_size) {
    const float* x       = (const float*)d_in[0];
    const float* proto   = (const float*)d_in[1];
    const float* conv_w  = (const float*)d_in[2];
    const float* conv_b  = (const float*)d_in[3];
    const float* lin_w   = (const float*)d_in[4];
    const float* lin_b   = (const float*)d_in[5];
    const float* warp_W  = (const float*)d_in[6];
    const float* warp_b  = (const float*)d_in[7];
    const float* off_W   = (const float*)d_in[8];
    const float* off_b   = (const float*)d_in[9];

    float* out = (float*)d_out;
    const size_t warped_elems = (size_t)B_ * K_ * T_ * C_; // 41,943,040
    float* out_warp = out + warped_elems;
    float* out_off  = out_warp + (size_t)B_ * K_;

    const int wsmem = T_ * 4 * sizeof(float4);   // 81920 B
    cudaFuncSetAttribute(warp_kernel,
                         cudaFuncAttributeMaxDynamicSharedMemorySize, wsmem);

    dim3 g1(POOL_, B_);
    conv_pool_kernel<<<g1, 256>>>(x, conv_w, conv_b);

    head_kernel<<<B_, 64>>>(lin_w, lin_b, warp_W, warp_b, off_W, off_b,
                            out_warp, out_off);

    dim3 g3(T_ / WT_, K_);
    warp_kernel<<<g3, 256, wsmem>>>(proto, (float4*)out);
}

// round 17
// speedup vs baseline: 1.5495x; 1.4947x over previous
#include <cuda_runtime.h>

#define B_ 64
#define K_ 32
#define T_ 1280
#define C_ 16
#define E_ 64
#define CONV_CH_ 32
#define POOL_ 10
#define SEG_ 128                 // T_ / POOL_
#define FEAT_ 320                // CONV_CH_ * POOL_

// scratch (no allocation allowed)
__device__ float g_warp[B_ * K_];
__device__ float g_off[B_ * K_];
__device__ float g_pool[B_ * FEAT_];

// ---------------------------------------------------------------------------
// Stage 1 (R13 exact, best measured 23.0us): conv1d(pad=2)+bias+relu+avgpool.
// Block per (pp, b). 8 warps: wg = w&1 channel half, tw = w>>1 t-range of 32.
// Lane: og=lane>>2, q=lane&3; thread owns channels o0,o0+1, quad q.
// t-pairs (tt, tt+16): 4 independent FMA chains + batched shfl reductions.
// ---------------------------------------------------------------------------
__global__ __launch_bounds__(256, 3) void conv_pool_kernel(
    const float* __restrict__ x,       // [B, T, C]
    const float* __restrict__ conv_w,  // [32, 16, 5]
    const float* __restrict__ conv_b)  // [32]
{
    __shared__ float4 sx4[(SEG_ + 4) * 4];     // 132 rows x 4 quads
    __shared__ float  sw[CONV_CH_ * 5 * C_];   // [o][kk][i]
    __shared__ float  sacc[4][CONV_CH_];       // per-tw pooled partials

    const int pp  = blockIdx.x;
    const int b   = blockIdx.y;
    const int tid = threadIdx.x;

    // stage conv weights rearranged: [o][i][kk] -> [o][kk][i]
    for (int idx = tid; idx < CONV_CH_ * C_ * 5; idx += 256) {
        int o   = idx / 80;
        int rem = idx - o * 80;
        int kk  = rem >> 4;
        int i   = rem & 15;
        sw[(o * 5 + kk) * C_ + i] = conv_w[o * 80 + i * 5 + kk];
    }

    // stage x tile: global rows pp*128-2 .. pp*128+129, zero outside [0,T)
    {
        const float4* x4 = (const float4*)(x + (size_t)b * T_ * C_);
        for (int idx = tid; idx < (SEG_ + 4) * 4; idx += 256) {
            int r = idx >> 2;
            int q = idx & 3;
            int g = pp * SEG_ - 2 + r;
            float4 v = make_float4(0.f, 0.f, 0.f, 0.f);
            if (g >= 0 && g < T_) v = x4[g * 4 + q];
            sx4[r * 4 + q] = v;
        }
    }
    __syncthreads();

    const int w    = tid >> 5;
    const int wg   = w & 1;             // channel half
    const int tw   = w >> 1;            // t range (32 t's)
    const int lane = tid & 31;
    const int og   = lane >> 2;
    const int q    = lane & 3;
    const int o0   = wg * 16 + og * 2;

    // weights: 2 channels x 5 taps, quad q -> 10 float4 (40 regs)
    float4 wreg[2][5];
    {
        const float4* sw4 = (const float4*)sw;
        #pragma unroll
        for (int j = 0; j < 2; ++j)
            #pragma unroll
            for (int kk = 0; kk < 5; ++kk)
                wreg[j][kk] = sw4[((o0 + j) * 5 + kk) * 4 + q];
    }
    const float bias0 = conv_b[o0];
    const float bias1 = conv_b[o0 + 1];

    float acc0 = 0.f, acc1 = 0.f;
    const int tbase = tw * 32;
    #pragma unroll 2
    for (int tt = 0; tt < 16; ++tt) {
        const int ra = tbase + tt;
        const int rb = ra + 16;
        float va0 = 0.f, va1 = 0.f, vb0 = 0.f, vb1 = 0.f;
        #pragma unroll
        for (int kk = 0; kk < 5; ++kk) {
            float4 xa = sx4[(ra + kk) * 4 + q];   // broadcast across og
            float4 xb = sx4[(rb + kk) * 4 + q];
            va0 = fmaf(xa.x, wreg[0][kk].x, va0); va0 = fmaf(xa.y, wreg[0][kk].y, va0);
            va0 = fmaf(xa.z, wreg[0][kk].z, va0); va0 = fmaf(xa.w, wreg[0][kk].w, va0);
            va1 = fmaf(xa.x, wreg[1][kk].x, va1); va1 = fmaf(xa.y, wreg[1][kk].y, va1);
            va1 = fmaf(xa.z, wreg[1][kk].z, va1); va1 = fmaf(xa.w, wreg[1][kk].w, va1);
            vb0 = fmaf(xb.x, wreg[0][kk].x, vb0); vb0 = fmaf(xb.y, wreg[0][kk].y, vb0);
            vb0 = fmaf(xb.z, wreg[0][kk].z, vb0); vb0 = fmaf(xb.w, wreg[0][kk].w, vb0);
            vb1 = fmaf(xb.x, wreg[1][kk].x, vb1); vb1 = fmaf(xb.y, wreg[1][kk].y, vb1);
            vb1 = fmaf(xb.z, wreg[1][kk].z, vb1); vb1 = fmaf(xb.w, wreg[1][kk].w, vb1);
        }
        va0 += __shfl_xor_sync(0xffffffffu, va0, 1);
        va1 += __shfl_xor_sync(0xffffffffu, va1, 1);
        vb0 += __shfl_xor_sync(0xffffffffu, vb0, 1);
        vb1 += __shfl_xor_sync(0xffffffffu, vb1, 1);
        va0 += __shfl_xor_sync(0xffffffffu, va0, 2);
        va1 += __shfl_xor_sync(0xffffffffu, va1, 2);
        vb0 += __shfl_xor_sync(0xffffffffu, vb0, 2);
        vb1 += __shfl_xor_sync(0xffffffffu, vb1, 2);
        acc0 += fmaxf(va0 + bias0, 0.f) + fmaxf(vb0 + bias0, 0.f);
        acc1 += fmaxf(va1 + bias1, 0.f) + fmaxf(vb1 + bias1, 0.f);
    }

    if (q == 0) {
        sacc[tw][o0]     = acc0;
        sacc[tw][o0 + 1] = acc1;
    }
    __syncthreads();
    if (tid < CONV_CH_) {
        float s = sacc[0][tid] + sacc[1][tid] + sacc[2][tid] + sacc[3][tid];
        g_pool[b * FEAT_ + tid * POOL_ + pp] = s * (1.f / SEG_);
    }
}

// ---------------------------------------------------------------------------
// Stage 2: linear+relu -> embed, then per-class warp/off scalars. Block per b.
// ---------------------------------------------------------------------------
__global__ __launch_bounds__(64) void head_kernel(
    const float* __restrict__ lin_w,   // [64, 320]
    const float* __restrict__ lin_b,   // [64]
    const float* __restrict__ warp_W,  // [32, 64]
    const float* __restrict__ warp_b,  // [32]
    const float* __restrict__ off_W,   // [32, 64]
    const float* __restrict__ off_b,   // [32]
    float* __restrict__ out_warp,      // tail of d_out
    float* __restrict__ out_off)
{
    __shared__ float4 sp[FEAT_ / 4];
    __shared__ float semb[E_];

    const int b   = blockIdx.x;
    const int tid = threadIdx.x;

    {
        const float4* gp = (const float4*)(g_pool + b * FEAT_);
        for (int j = tid; j < FEAT_ / 4; j += 64) sp[j] = gp[j];
    }
    __syncthreads();

    {
        const float4* wr = (const float4*)(lin_w + (size_t)tid * FEAT_);
        float a0 = lin_b[tid], a1 = 0.f;
        #pragma unroll 4
        for (int j = 0; j < FEAT_ / 4; j += 2) {
            float4 w0 = wr[j],   p0 = sp[j];
            float4 w1 = wr[j+1], p1 = sp[j+1];
            a0 = fmaf(w0.x, p0.x, a0); a0 = fmaf(w0.y, p0.y, a0);
            a0 = fmaf(w0.z, p0.z, a0); a0 = fmaf(w0.w, p0.w, a0);
            a1 = fmaf(w1.x, p1.x, a1); a1 = fmaf(w1.y, p1.y, a1);
            a1 = fmaf(w1.z, p1.z, a1); a1 = fmaf(w1.w, p1.w, a1);
        }
        semb[tid] = fmaxf(a0 + a1, 0.f);
    }
    __syncthreads();

    if (tid < K_) {
        const float* wW = warp_W + tid * E_;
        const float* oW = off_W + tid * E_;
        float aw = warp_b[tid];
        float ao = off_b[tid];
        #pragma unroll
        for (int e = 0; e < E_; ++e) {
            float em = semb[e];
            aw = fmaf(wW[e], em, aw);
            ao = fmaf(oW[e], em, ao);
        }
        const int bk = b * K_ + tid;
        g_warp[bk] = aw;
        g_off[bk]  = ao;
        out_warp[bk] = aw;
        out_off[bk]  = ao;
    }
}

// ---------------------------------------------------------------------------
// Stage 3: warped output. R1 structure (best measured 40.5us) + 2 outputs per
// thread at t and t+640 in the same bk: two independent LDG/FMA/STG chains,
// stores stay 512B-coalesced per warp, proto reads are L2 hits.
// ---------------------------------------------------------------------------
__global__ __launch_bounds__(256) void warp_kernel(
    const float* __restrict__ proto,   // [K, T, C]
    float4* __restrict__ out)          // [B, K, T, C] as float4
{
    const unsigned tid = blockIdx.x * 256u + threadIdx.x;   // < B*K*640*4
    const unsigned q  = tid & 3u;
    const unsigned r  = tid >> 2;          // b*K*640 + k*640 + tt
    const unsigned tt = r % 640u;
    const unsigned bk = r / 640u;          // b*K + k
    const unsigned k  = bk & (K_ - 1);

    const float w = g_warp[bk];
    const float o = g_off[bk];

    const float4* pk = (const float4*)(proto + (size_t)k * T_ * C_);
    float4* ob = out + ((size_t)bk * T_) * 4;

    // two independent chains: t = tt and t = tt + 640
    float idxA = fminf(fmaxf((float)tt - w, 0.f), (float)(T_ - 1));
    float idxB = fminf(fmaxf((float)(tt + 640) - w, 0.f), (float)(T_ - 1));
    float iA0f = floorf(idxA);
    float iB0f = floorf(idxB);
    int iA0 = (int)iA0f, iB0 = (int)iB0f;
    int iA1 = min(iA0 + 1, T_ - 1);
    int iB1 = min(iB0 + 1, T_ - 1);
    float fA = idxA - iA0f, fB = idxB - iB0f;

    float4 aA = pk[iA0 * 4 + q];
    float4 cA = pk[iA1 * 4 + q];
    float4 aB = pk[iB0 * 4 + q];
    float4 cB = pk[iB1 * 4 + q];

    float4 rA, rB;
    rA.x = fmaf(fA, cA.x - aA.x, aA.x) + o;
    rA.y = fmaf(fA, cA.y - aA.y, aA.y) + o;
    rA.z = fmaf(fA, cA.z - aA.z, aA.z) + o;
    rA.w = fmaf(fA, cA.w - aA.w, aA.w) + o;
    rB.x = fmaf(fB, cB.x - aB.x, aB.x) + o;
    rB.y = fmaf(fB, cB.y - aB.y, aB.y) + o;
    rB.z = fmaf(fB, cB.z - aB.z, aB.z) + o;
    rB.w = fmaf(fB, cB.w - aB.w, aB.w) + o;

    ob[tt * 4 + q] = rA;
    ob[(tt + 640) * 4 + q] = rB;
}

extern "C" void kernel_launch(void* const* d_in, const int* in_sizes, int n_in,
                              void* d_out, int out_size) {
    const float* x       = (const float*)d_in[0];
    const float* proto   = (const float*)d_in[1];
    const float* conv_w  = (const float*)d_in[2];
    const float* conv_b  = (const float*)d_in[3];
    const float* lin_w   = (const float*)d_in[4];
    const float* lin_b   = (const float*)d_in[5];
    const float* warp_W  = (const float*)d_in[6];
    const float* warp_b  = (const float*)d_in[7];
    const float* off_W   = (const float*)d_in[8];
    const float* off_b   = (const float*)d_in[9];

    float* out = (float*)d_out;
    const size_t warped_elems = (size_t)B_ * K_ * T_ * C_; // 41,943,040
    float* out_warp = out + warped_elems;
    float* out_off  = out_warp + (size_t)B_ * K_;

    dim3 g1(POOL_, B_);
    conv_pool_kernel<<<g1, 256>>>(x, conv_w, conv_b);

    head_kernel<<<B_, 64>>>(lin_w, lin_b, warp_W, warp_b, off_W, off_b,
                            out_warp, out_off);

    const unsigned total = (unsigned)(B_ * K_ * 640 * 4); // 5,242,880 threads
    warp_kernel<<<total / 256, 256>>>(proto, (float4*)out);
}